// round 1
// baseline (speedup 1.0000x reference)
#include <cuda_runtime.h>
#include <cstdint>
#include <cstring>

// Problem constants
#define SLEN 8192
#define EDIM 512
#define HDIM 256
#define G4   1024   // 4*H
#define NTAG 16
#define NEGV (-10000.0f)
#define START_ID 14
#define STOP_ID  15
#define SENTINEL 2.0f   // |h| < 1 always (tanh-bounded), so 2.0 is unreachable

// ---------------- scratch (device globals; no allocations) ----------------
__device__ float g_xg[2][SLEN][G4];          // precomputed input projections (+bias)
__device__ float g_hs[2][SLEN][HDIM];        // hs[0][t]=fwd h_t ; hs[1][t]=bwd h at forward-time t
__device__ float g_feats[SLEN + 8][NTAG];    // padded for viterbi prefetch

// ---------------- small asm helpers ----------------
__device__ __forceinline__ void fma2(unsigned long long& acc, unsigned long long a,
                                     unsigned long long b) {
    asm("fma.rn.f32x2 %0, %1, %2, %0;" : "+l"(acc) : "l"(a), "l"(b));
}
__device__ __forceinline__ unsigned long long pack2(float x, float y) {
    unsigned long long r;
    asm("mov.b64 %0, {%1, %2};" : "=l"(r) : "f"(x), "f"(y));
    return r;
}
__device__ __forceinline__ float2 unpack2(unsigned long long v) {
    float2 r;
    asm("mov.b64 {%0, %1}, %2;" : "=f"(r.x), "=f"(r.y) : "l"(v));
    return r;
}
__device__ __forceinline__ void st_release_f32(float* p, float v) {
    asm volatile("st.release.gpu.global.f32 [%0], %1;" :: "l"(p), "f"(v) : "memory");
}
__device__ __forceinline__ float ld_acquire_f32(const float* p) {
    float v;
    asm volatile("ld.acquire.gpu.global.f32 %0, [%1];" : "=f"(v) : "l"(p) : "memory");
    return v;
}
__device__ __forceinline__ float ld_cg_f32(const float* p) {
    float v;
    asm volatile("ld.global.cg.f32 %0, [%1];" : "=f"(v) : "l"(p) : "memory");
    return v;
}
__device__ __forceinline__ float fast_sigmoid(float x) {
    return 1.0f / (1.0f + __expf(-x));
}
__device__ __forceinline__ float fast_tanh(float x) {
    return 2.0f / (1.0f + __expf(-2.0f * x)) - 1.0f;
}

// ---------------- kernel 1: sentinel init ----------------
__global__ void k_init() {
    int idx = blockIdx.x * blockDim.x + threadIdx.x;
    int total = 2 * SLEN * 8;
    if (idx < total) {
        int dir = idx / (SLEN * 8);
        int rem = idx % (SLEN * 8);
        int t = rem / 8;
        int r = rem % 8;
        g_hs[dir][t][r * 32] = SENTINEL;
    }
}

// ---------------- kernel 2: xg = gather(embedding) @ Wih.T + (bih+bhh) ----------------
#define BM 64
#define BN 64
#define BK 32
__global__ void __launch_bounds__(256) k_xg(
    const int* __restrict__ sent, const float* __restrict__ emb,
    const float* __restrict__ WihF, const float* __restrict__ WihB,
    const float* __restrict__ bihF, const float* __restrict__ bhhF,
    const float* __restrict__ bihB, const float* __restrict__ bhhB) {
    int dir = blockIdx.z;
    int t0 = blockIdx.y * BM;
    int n0 = blockIdx.x * BN;
    const float* Wih = dir ? WihB : WihF;

    __shared__ float As[BK][BM + 4];
    __shared__ float Bs[BK][BN + 4];
    __shared__ int sidx[BM];
    __shared__ float biassm[BN];

    int tid = threadIdx.x;  // 256
    if (tid < BM) {
        int t = t0 + tid;
        int s = dir ? (SLEN - 1 - t) : t;
        sidx[tid] = sent[s];
    }
    if (tid < BN) {
        int n = n0 + tid;
        biassm[tid] = dir ? (bihB[n] + bhhB[n]) : (bihF[n] + bhhF[n]);
    }
    __syncthreads();

    float acc[4][4];
#pragma unroll
    for (int i = 0; i < 4; i++)
#pragma unroll
        for (int j = 0; j < 4; j++) acc[i][j] = 0.0f;

    int tm = (tid & 15) * 4;
    int tn = (tid >> 4) * 4;
    int lm = tid >> 2;           // 0..63 : row (t or n) for loading
    int lk = (tid & 3) * 8;      // k offset in tile

    for (int k0 = 0; k0 < EDIM; k0 += BK) {
        // A tile: gathered embedding rows
        {
            const float4* src = (const float4*)(emb + (size_t)sidx[lm] * EDIM + k0 + lk);
            float4 a0 = src[0], a1 = src[1];
            As[lk + 0][lm] = a0.x; As[lk + 1][lm] = a0.y;
            As[lk + 2][lm] = a0.z; As[lk + 3][lm] = a0.w;
            As[lk + 4][lm] = a1.x; As[lk + 5][lm] = a1.y;
            As[lk + 6][lm] = a1.z; As[lk + 7][lm] = a1.w;
        }
        // B tile: Wih rows
        {
            const float4* src = (const float4*)(Wih + (size_t)(n0 + lm) * EDIM + k0 + lk);
            float4 b0 = src[0], b1 = src[1];
            Bs[lk + 0][lm] = b0.x; Bs[lk + 1][lm] = b0.y;
            Bs[lk + 2][lm] = b0.z; Bs[lk + 3][lm] = b0.w;
            Bs[lk + 4][lm] = b1.x; Bs[lk + 5][lm] = b1.y;
            Bs[lk + 6][lm] = b1.z; Bs[lk + 7][lm] = b1.w;
        }
        __syncthreads();
#pragma unroll
        for (int kk = 0; kk < BK; kk++) {
            float4 av = *(const float4*)&As[kk][tm];
            float4 bv = *(const float4*)&Bs[kk][tn];
            float a[4] = {av.x, av.y, av.z, av.w};
            float b[4] = {bv.x, bv.y, bv.z, bv.w};
#pragma unroll
            for (int i = 0; i < 4; i++)
#pragma unroll
                for (int j = 0; j < 4; j++) acc[i][j] += a[i] * b[j];
        }
        __syncthreads();
    }
#pragma unroll
    for (int i = 0; i < 4; i++)
#pragma unroll
        for (int j = 0; j < 4; j++)
            g_xg[dir][t0 + tm + i][n0 + tn + j] = acc[i][j] + biassm[tn + j];
}

// ---------------- kernel 3: the bidirectional LSTM recurrence ----------------
// 16 CTAs: blockIdx.x/8 = direction, blockIdx.x%8 = h-slice r (owns h[32r..32r+31]).
// Weights register-resident; cross-CTA h exchange via L2 (write-once addresses,
// release head / acquire-poll protocol with sentinel).
__global__ void __launch_bounds__(256, 1) k_lstm(
    const float* __restrict__ WhhF, const float* __restrict__ WhhB,
    const float* __restrict__ h0, const float* __restrict__ c0) {
    int dir = blockIdx.x >> 3;
    int r = blockIdx.x & 7;
    int tid = threadIdx.x;
    int half = tid >> 7;       // which 128-column half of h
    int lr = tid & 127;        // local gate-row
    int q = lr >> 5;           // gate (i,f,g,o)
    int j = lr & 31;           // h-element within slice
    int grow = q * 256 + r * 32 + j;  // global row of Whh / xg

    const float* Whh = dir ? WhhB : WhhF;

    __shared__ __align__(16) float hsm[256];
    __shared__ float redsm[128];
    __shared__ float gsm[128];

    // register-resident weight slice: 128 floats = 64 packed f32x2
    unsigned long long wl[64];
    {
        const float2* wrow = (const float2*)(Whh + (size_t)grow * HDIM) + half * 64;
#pragma unroll
        for (int m = 0; m < 64; m++) {
            float2 v = wrow[m];
            wl[m] = pack2(v.x, v.y);
        }
    }

    // initial state
    hsm[tid] = h0[dir * HDIM + tid];
    float c = 0.0f;
    if (tid < 32) c = c0[dir * HDIM + r * 32 + tid];
    float xcur = 0.0f;
    if (half == 0) xcur = g_xg[dir][0][grow];
    __syncthreads();

    const ulonglong2* hsm2 = (const ulonglong2*)hsm;
    int base = half * 32;

#pragma unroll 1
    for (int t = 0; t < SLEN; t++) {
        // ---- matvec partial: 128 MACs via 64 packed fma.f32x2 ----
        unsigned long long a0 = 0ull, a1 = 0ull, a2 = 0ull, a3 = 0ull;
#pragma unroll
        for (int m = 0; m < 32; m++) {
            ulonglong2 hv = hsm2[base + m];
            if (m & 1) { fma2(a2, wl[2 * m], hv.x); fma2(a3, wl[2 * m + 1], hv.y); }
            else       { fma2(a0, wl[2 * m], hv.x); fma2(a1, wl[2 * m + 1], hv.y); }
        }
        float2 f0 = unpack2(a0), f1 = unpack2(a1), f2 = unpack2(a2), f3 = unpack2(a3);
        float part = ((f0.x + f0.y) + (f1.x + f1.y)) + ((f2.x + f2.y) + (f3.x + f3.y));
        if (half == 1) redsm[lr] = part;
        __syncthreads();

        if (half == 0) {
            float gate = part + redsm[lr] + xcur;
            gsm[lr] = gate;
            if (t + 1 < SLEN) xcur = g_xg[dir][t + 1][grow];  // prefetch next step
        }
        __syncthreads();

        int tstore = dir ? (SLEN - 1 - t) : t;
        if (tid < 32) {
            // cell update for h-elements r*32 + tid
            float gi = gsm[tid], gf = gsm[32 + tid], gg = gsm[64 + tid], go = gsm[96 + tid];
            float ig = fast_sigmoid(gi);
            float fg = fast_sigmoid(gf);
            float gv = fast_tanh(gg);
            float og = fast_sigmoid(go);
            c = fg * c + ig * gv;
            float h = og * fast_tanh(c);
            hsm[r * 32 + tid] = h;
            float* dst = &g_hs[dir][tstore][r * 32];
            if (tid != 0) dst[tid] = h;
            __syncwarp();
            if (tid == 0) st_release_f32(dst, h);   // head last, release: data-as-flag
        } else if (t + 1 < SLEN) {
            // warps 1..7: fetch the 7 peer slices of h_t for next step
            int w = tid >> 5;                 // 1..7
            int peer = (r + w) & 7;
            int lane = tid & 31;
            const float* src = &g_hs[dir][tstore][peer * 32];
            float v0 = 0.0f;
            if (lane == 0) {
                do { v0 = ld_acquire_f32(src); } while (v0 == SENTINEL);
            }
            __syncwarp();
            float v = (lane == 0) ? v0 : ld_cg_f32(src + lane);
            hsm[peer * 32 + lane] = v;
        }
        __syncthreads();
    }
}

// ---------------- kernel 4: feats[t] = concat(hf,hb) @ W_tag.T + b_tag ----------------
__global__ void __launch_bounds__(128) k_feats(const float* __restrict__ Wt,
                                               const float* __restrict__ bt) {
    int t = blockIdx.x;
    __shared__ float hsm[512];
    __shared__ float Wsm[NTAG * 513];
    int tid = threadIdx.x;  // 128
    {
        float4* h4 = (float4*)hsm;
        if (tid < 64) h4[tid] = ((const float4*)g_hs[0][t])[tid];
        else h4[tid] = ((const float4*)g_hs[1][t])[tid - 64];
    }
    for (int i = tid; i < NTAG * 512; i += 128) {
        int tg = i >> 9, k = i & 511;
        Wsm[tg * 513 + k] = Wt[i];
    }
    __syncthreads();
    int tg = tid >> 3, seg = tid & 7;
    float acc = 0.0f;
#pragma unroll 8
    for (int m = 0; m < 64; m++) {
        int k = seg + 8 * m;  // stride-8: conflict-free banks
        acc += hsm[k] * Wsm[tg * 513 + k];
    }
    acc += __shfl_xor_sync(0xffffffff, acc, 1);
    acc += __shfl_xor_sync(0xffffffff, acc, 2);
    acc += __shfl_xor_sync(0xffffffff, acc, 4);
    if (seg == 0) g_feats[t][tg] = acc + bt[tg];
}

// ---------------- kernel 5: Viterbi + backtrace (1 warp) ----------------
__global__ void k_viterbi(const float* __restrict__ trans, float* __restrict__ out,
                          int out_size) {
    extern __shared__ unsigned char bp[];  // [SLEN][16] backpointers
    int lane = threadIdx.x;                // 32 threads
    int i = lane & 15;

    float tr[16];
#pragma unroll
    for (int j2 = 0; j2 < 16; j2++) tr[j2] = trans[i * 16 + j2];

    float fv = (i == START_ID) ? 0.0f : NEGV;

    // software prefetch pipeline, depth 4
    float fpre[4];
#pragma unroll
    for (int p = 0; p < 4; p++) fpre[p] = g_feats[p][i];

    for (int t = 0; t < SLEN; t += 4) {
#pragma unroll
        for (int u = 0; u < 4; u++) {
            float v[16];
            int idx[16];
#pragma unroll
            for (int j2 = 0; j2 < 16; j2++) {
                v[j2] = __shfl_sync(0xffffffff, fv, j2) + tr[j2];
                idx[j2] = j2;
            }
            // argmax tree (strict > keeps first-max index, matching jnp.argmax)
#pragma unroll
            for (int stride = 1; stride < 16; stride <<= 1) {
#pragma unroll
                for (int j2 = 0; j2 < 16; j2 += 2 * stride) {
                    if (v[j2 + stride] > v[j2]) {
                        v[j2] = v[j2 + stride];
                        idx[j2] = idx[j2 + stride];
                    }
                }
            }
            if (lane < 16) bp[(t + u) * 16 + i] = (unsigned char)idx[0];
            fv = v[0] + fpre[u];
            fpre[u] = g_feats[t + u + 4][i];  // padded array: always in-bounds
        }
    }

    // terminal
    float tv = (lane < 16) ? (fv + trans[STOP_ID * 16 + i]) : -3.4e38f;
    int ti = i;
#pragma unroll
    for (int s = 8; s >= 1; s >>= 1) {
        float ov = __shfl_down_sync(0xffffffff, tv, s);
        int oi = __shfl_down_sync(0xffffffff, ti, s);
        if (ov > tv || (ov == tv && oi < ti)) { tv = ov; ti = oi; }
    }
    if (lane == 0) {
        if (out_size > 0) out[0] = tv;
        int tag = ti;
        for (int t = SLEN - 1; t >= 0; t--) {
            if (1 + t < out_size) out[1 + t] = (float)tag;
            tag = bp[t * 16 + tag];
        }
    }
}

// ---------------- launch ----------------
extern "C" void kernel_launch(void* const* d_in, const int* in_sizes, int n_in,
                              void* d_out, int out_size) {
    const int*   sent = (const int*)d_in[0];
    const float* emb  = (const float*)d_in[1];
    const float* WihF = (const float*)d_in[2];
    const float* WhhF = (const float*)d_in[3];
    const float* bihF = (const float*)d_in[4];
    const float* bhhF = (const float*)d_in[5];
    const float* WihB = (const float*)d_in[6];
    const float* WhhB = (const float*)d_in[7];
    const float* bihB = (const float*)d_in[8];
    const float* bhhB = (const float*)d_in[9];
    const float* h0   = (const float*)d_in[10];
    const float* c0   = (const float*)d_in[11];
    const float* Wt   = (const float*)d_in[12];
    const float* bt   = (const float*)d_in[13];
    const float* trn  = (const float*)d_in[14];
    float* out = (float*)d_out;

    cudaFuncSetAttribute(k_viterbi, cudaFuncAttributeMaxDynamicSharedMemorySize,
                         SLEN * 16 + 1024);

    k_init<<<(2 * SLEN * 8 + 255) / 256, 256>>>();

    dim3 gxg(G4 / BN, SLEN / BM, 2);
    k_xg<<<gxg, 256>>>(sent, emb, WihF, WihB, bihF, bhhF, bihB, bhhB);

    k_lstm<<<16, 256>>>(WhhF, WhhB, h0, c0);

    k_feats<<<SLEN, 128>>>(Wt, bt);

    k_viterbi<<<1, 32, SLEN * 16>>>(trn, out, out_size);
}

// round 2
// speedup vs baseline: 1.7463x; 1.7463x over previous
#include <cuda_runtime.h>
#include <cstdint>

// Problem constants
#define SLEN 8192
#define EDIM 512
#define HDIM 256
#define G4   1024   // 4*H
#define NTAG 16
#define NEGV (-10000.0f)
#define START_ID 14
#define STOP_ID  15

// ---------------- scratch (device globals; no allocations) ----------------
__device__ float g_xg[2][SLEN][G4];          // precomputed input projections (+bias)
__device__ float g_hs[2][SLEN][HDIM];        // hs[0][t]=fwd h_t ; hs[1][t]=bwd h at forward-time t
__device__ float g_feats[SLEN + 8][NTAG];    // padded for viterbi prefetch

// ---------------- small asm helpers ----------------
__device__ __forceinline__ void fma2(unsigned long long& acc, unsigned long long a,
                                     unsigned long long b) {
    asm("fma.rn.f32x2 %0, %1, %2, %0;" : "+l"(acc) : "l"(a), "l"(b));
}
__device__ __forceinline__ unsigned long long pack2(float x, float y) {
    unsigned long long r;
    asm("mov.b64 %0, {%1, %2};" : "=l"(r) : "f"(x), "f"(y));
    return r;
}
__device__ __forceinline__ float2 unpack2(unsigned long long v) {
    float2 r;
    asm("mov.b64 {%0, %1}, %2;" : "=f"(r.x), "=f"(r.y) : "l"(v));
    return r;
}
__device__ __forceinline__ float fast_sigmoid(float x) {
    return 1.0f / (1.0f + __expf(-x));
}
__device__ __forceinline__ float fast_tanh(float x) {
    return 2.0f / (1.0f + __expf(-2.0f * x)) - 1.0f;
}
__device__ __forceinline__ uint32_t smem_u32(const void* p) {
    uint32_t a;
    asm("{ .reg .u64 t; cvta.to.shared.u64 t, %1; cvt.u32.u64 %0, t; }"
        : "=r"(a) : "l"(p));
    return a;
}
__device__ __forceinline__ uint32_t mapa_rank(uint32_t addr, uint32_t rank) {
    uint32_t r;
    asm("mapa.shared::cluster.u32 %0, %1, %2;" : "=r"(r) : "r"(addr), "r"(rank));
    return r;
}
__device__ __forceinline__ void st_async_f32(uint32_t daddr, float v, uint32_t maddr) {
    asm volatile(
        "st.async.shared::cluster.mbarrier::complete_tx::bytes.b32 [%0], %1, [%2];"
        :: "r"(daddr), "r"(__float_as_uint(v)), "r"(maddr) : "memory");
}
__device__ __forceinline__ void mbar_init(uint32_t maddr, uint32_t cnt) {
    asm volatile("mbarrier.init.shared.b64 [%0], %1;" :: "r"(maddr), "r"(cnt) : "memory");
}
__device__ __forceinline__ void mbar_expect(uint32_t maddr, uint32_t bytes) {
    asm volatile("mbarrier.arrive.expect_tx.shared.b64 _, [%0], %1;"
                 :: "r"(maddr), "r"(bytes) : "memory");
}
__device__ __forceinline__ void mbar_wait(uint32_t maddr, uint32_t parity) {
    asm volatile(
        "{\n\t.reg .pred P1;\n\t"
        "WL%=:\n\t"
        "mbarrier.try_wait.parity.acquire.cta.shared::cta.b64 P1, [%0], %1, 0x989680;\n\t"
        "@P1 bra WD%=;\n\t"
        "bra WL%=;\n\t"
        "WD%=:\n\t}"
        :: "r"(maddr), "r"(parity) : "memory");
}
#define CLUSTER_SYNC() do { \
    asm volatile("barrier.cluster.arrive.aligned;" ::: "memory"); \
    asm volatile("barrier.cluster.wait.aligned;" ::: "memory"); } while (0)

// ---------------- kernel 1: xg = gather(embedding) @ Wih.T + (bih+bhh) ----------------
#define BM 64
#define BN 64
#define BK 32
__global__ void __launch_bounds__(256) k_xg(
    const int* __restrict__ sent, const float* __restrict__ emb,
    const float* __restrict__ WihF, const float* __restrict__ WihB,
    const float* __restrict__ bihF, const float* __restrict__ bhhF,
    const float* __restrict__ bihB, const float* __restrict__ bhhB) {
    int dir = blockIdx.z;
    int t0 = blockIdx.y * BM;
    int n0 = blockIdx.x * BN;
    const float* Wih = dir ? WihB : WihF;

    __shared__ float As[BK][BM + 4];
    __shared__ float Bs[BK][BN + 4];
    __shared__ int sidx[BM];
    __shared__ float biassm[BN];

    int tid = threadIdx.x;  // 256
    if (tid < BM) {
        int t = t0 + tid;
        int s = dir ? (SLEN - 1 - t) : t;
        sidx[tid] = sent[s];
    }
    if (tid < BN) {
        int n = n0 + tid;
        biassm[tid] = dir ? (bihB[n] + bhhB[n]) : (bihF[n] + bhhF[n]);
    }
    __syncthreads();

    float acc[4][4];
#pragma unroll
    for (int i = 0; i < 4; i++)
#pragma unroll
        for (int j = 0; j < 4; j++) acc[i][j] = 0.0f;

    int tm = (tid & 15) * 4;
    int tn = (tid >> 4) * 4;
    int lm = tid >> 2;           // 0..63 : row (t or n) for loading
    int lk = (tid & 3) * 8;      // k offset in tile

    for (int k0 = 0; k0 < EDIM; k0 += BK) {
        {
            const float4* src = (const float4*)(emb + (size_t)sidx[lm] * EDIM + k0 + lk);
            float4 a0 = src[0], a1 = src[1];
            As[lk + 0][lm] = a0.x; As[lk + 1][lm] = a0.y;
            As[lk + 2][lm] = a0.z; As[lk + 3][lm] = a0.w;
            As[lk + 4][lm] = a1.x; As[lk + 5][lm] = a1.y;
            As[lk + 6][lm] = a1.z; As[lk + 7][lm] = a1.w;
        }
        {
            const float4* src = (const float4*)(Wih + (size_t)(n0 + lm) * EDIM + k0 + lk);
            float4 b0 = src[0], b1 = src[1];
            Bs[lk + 0][lm] = b0.x; Bs[lk + 1][lm] = b0.y;
            Bs[lk + 2][lm] = b0.z; Bs[lk + 3][lm] = b0.w;
            Bs[lk + 4][lm] = b1.x; Bs[lk + 5][lm] = b1.y;
            Bs[lk + 6][lm] = b1.z; Bs[lk + 7][lm] = b1.w;
        }
        __syncthreads();
#pragma unroll
        for (int kk = 0; kk < BK; kk++) {
            float4 av = *(const float4*)&As[kk][tm];
            float4 bv = *(const float4*)&Bs[kk][tn];
            float a[4] = {av.x, av.y, av.z, av.w};
            float b[4] = {bv.x, bv.y, bv.z, bv.w};
#pragma unroll
            for (int i = 0; i < 4; i++)
#pragma unroll
                for (int j = 0; j < 4; j++) acc[i][j] += a[i] * b[j];
        }
        __syncthreads();
    }
#pragma unroll
    for (int i = 0; i < 4; i++)
#pragma unroll
        for (int j = 0; j < 4; j++)
            g_xg[dir][t0 + tm + i][n0 + tn + j] = acc[i][j] + biassm[tn + j];
}

// ---------------- kernel 2: the bidirectional LSTM recurrence (cluster + DSMEM) ----------------
// Grid = 16 CTAs, cluster (8,1,1): cluster 0 = forward dir, cluster 1 = backward.
// CTA rank r owns h elements [32r, 32r+32) and gate rows {q*256 + r*32 + j}.
// Thread layout: warp w handles local gate rows lr = w*16 + (lane>>1); lane parity
// selects which 128-wide half of h the thread's dot-product covers (combined by shfl).
// h exchange: warp 0 st.async's its 32 h values into all 8 CTAs' double-buffered
// smem h buffer; per-CTA mbarrier expects 8*32*4 = 1024 bytes per step.

template <int P>
__device__ __forceinline__ void lstm_step(
    int t, int dir, int r, int tid, int wid, int lane, int half, int lr, int grow,
    const unsigned long long* __restrict__ wl,
    float (*hbuf)[256], float (*gsm)[128],
    uint32_t mb_cur, uint32_t mb_nxt, uint32_t& ph_cur,
    const uint32_t dd[8], const uint32_t dm[8],
    float& c, float& xcur) {
    if (t > 0) { mbar_wait(mb_cur, ph_cur); ph_cur ^= 1; }
    if (tid == 0 && t + 1 < SLEN) mbar_expect(mb_nxt, 1024);

    // ---- matvec half-row: 128 MACs via 64 packed fma.f32x2; h via smem broadcast ----
    const ulonglong2* h2 = (const ulonglong2*)&hbuf[P][half * 128];
    unsigned long long a0 = 0ull, a1 = 0ull, a2 = 0ull, a3 = 0ull;
#pragma unroll
    for (int m = 0; m < 32; m++) {
        ulonglong2 hv = h2[m];
        if (m & 1) { fma2(a2, wl[2 * m], hv.x); fma2(a3, wl[2 * m + 1], hv.y); }
        else       { fma2(a0, wl[2 * m], hv.x); fma2(a1, wl[2 * m + 1], hv.y); }
    }
    float2 f0 = unpack2(a0), f1 = unpack2(a1), f2 = unpack2(a2), f3 = unpack2(a3);
    float part = ((f0.x + f0.y) + (f1.x + f1.y)) + ((f2.x + f2.y) + (f3.x + f3.y));
    float tot = part + __shfl_xor_sync(0xffffffffu, part, 1);
    if (half == 0) {
        gsm[P][lr] = tot + xcur;
        if (t + 1 < SLEN) xcur = g_xg[dir][t + 1][grow];   // prefetch next step
    }
    __syncthreads();

    if (wid == 0) {
        float gi = gsm[P][lane],      gf = gsm[P][32 + lane];
        float gg = gsm[P][64 + lane], go = gsm[P][96 + lane];
        float ig = fast_sigmoid(gi);
        float fg = fast_sigmoid(gf);
        float gv = fast_tanh(gg);
        float og = fast_sigmoid(go);
        c = fg * c + ig * gv;
        float h = og * fast_tanh(c);
        int tstore = dir ? (SLEN - 1 - t) : t;
        g_hs[dir][tstore][r * 32 + lane] = h;
        if (t + 1 < SLEN) {
#pragma unroll
            for (int k = 0; k < 8; k++) st_async_f32(dd[k], h, dm[k]);
        }
    }
}

__global__ void __launch_bounds__(256, 1) __cluster_dims__(8, 1, 1)
k_lstm(const float* __restrict__ WhhF, const float* __restrict__ WhhB,
       const float* __restrict__ h0, const float* __restrict__ c0) {
    int dir = blockIdx.x >> 3;
    int r = blockIdx.x & 7;            // == cluster rank
    int tid = threadIdx.x;
    int wid = tid >> 5, lane = tid & 31;
    int half = lane & 1;
    int lr = wid * 16 + (lane >> 1);   // local gate row 0..127
    int q = lr >> 5, j = lr & 31;
    int grow = q * 256 + r * 32 + j;   // global gate row in Whh / xg
    const float* Whh = dir ? WhhB : WhhF;

    __shared__ __align__(16) float hbuf[2][256];
    __shared__ float gsm[2][128];
    __shared__ __align__(8) unsigned long long mbar[2];

    // register-resident weight half-row: 128 floats = 64 packed f32x2
    unsigned long long wl[64];
    {
        const float2* wrow = (const float2*)(Whh + (size_t)grow * HDIM) + half * 64;
#pragma unroll
        for (int m = 0; m < 64; m++) { float2 v = wrow[m]; wl[m] = pack2(v.x, v.y); }
    }

    uint32_t hb0 = smem_u32(&hbuf[0][0]), hb1 = smem_u32(&hbuf[1][0]);
    uint32_t mb0 = smem_u32(&mbar[0]),    mb1 = smem_u32(&mbar[1]);
    if (tid == 0) { mbar_init(mb0, 1); mbar_init(mb1, 1); }
    hbuf[0][tid] = h0[dir * HDIM + tid];

    float c = 0.0f;
    uint32_t dd0[8], dd1[8], dm0[8], dm1[8];
#pragma unroll
    for (int k = 0; k < 8; k++) { dd0[k] = dd1[k] = dm0[k] = dm1[k] = 0u; }
    if (wid == 0) {
        c = c0[dir * HDIM + r * 32 + lane];
        uint32_t off = (uint32_t)(r * 32 + lane) * 4u;
#pragma unroll
        for (int k = 0; k < 8; k++) {
            dd0[k] = mapa_rank(hb0 + off, (uint32_t)k);
            dd1[k] = mapa_rank(hb1 + off, (uint32_t)k);
            dm0[k] = mapa_rank(mb0, (uint32_t)k);
            dm1[k] = mapa_rank(mb1, (uint32_t)k);
        }
    }
    float xcur = (half == 0) ? g_xg[dir][0][grow] : 0.0f;

    CLUSTER_SYNC();   // mbarriers + hbuf[0] visible cluster-wide before any st.async

    uint32_t ph0 = 0, ph1 = 0;
#pragma unroll 1
    for (int t = 0; t < SLEN; t += 2) {
        lstm_step<0>(t,     dir, r, tid, wid, lane, half, lr, grow, wl, hbuf, gsm,
                     mb0, mb1, ph0, dd1, dm1, c, xcur);
        lstm_step<1>(t + 1, dir, r, tid, wid, lane, half, lr, grow, wl, hbuf, gsm,
                     mb1, mb0, ph1, dd0, dm0, c, xcur);
    }
    CLUSTER_SYNC();   // no CTA exits while peers' st.async may be in flight
}

// ---------------- kernel 3: feats[t] = concat(hf,hb) @ W_tag.T + b_tag ----------------
__global__ void __launch_bounds__(128) k_feats(const float* __restrict__ Wt,
                                               const float* __restrict__ bt) {
    int t = blockIdx.x;
    __shared__ float hsm[512];
    __shared__ float Wsm[NTAG * 513];
    int tid = threadIdx.x;  // 128
    {
        float4* h4 = (float4*)hsm;
        if (tid < 64) h4[tid] = ((const float4*)g_hs[0][t])[tid];
        else h4[tid] = ((const float4*)g_hs[1][t])[tid - 64];
    }
    for (int i = tid; i < NTAG * 512; i += 128) {
        int tg = i >> 9, k = i & 511;
        Wsm[tg * 513 + k] = Wt[i];
    }
    __syncthreads();
    int tg = tid >> 3, seg = tid & 7;
    float acc = 0.0f;
#pragma unroll 8
    for (int m = 0; m < 64; m++) {
        int k = seg + 8 * m;  // stride-8: conflict-free banks
        acc += hsm[k] * Wsm[tg * 513 + k];
    }
    acc += __shfl_xor_sync(0xffffffff, acc, 1);
    acc += __shfl_xor_sync(0xffffffff, acc, 2);
    acc += __shfl_xor_sync(0xffffffff, acc, 4);
    if (seg == 0) g_feats[t][tg] = acc + bt[tg];
}

// ---------------- kernel 4: Viterbi + backtrace (1 warp) ----------------
__global__ void k_viterbi(const float* __restrict__ trans, float* __restrict__ out,
                          int out_size) {
    extern __shared__ unsigned char bp[];  // [SLEN][16] backpointers
    int lane = threadIdx.x;                // 32 threads
    int i = lane & 15;

    float tr[16];
#pragma unroll
    for (int j2 = 0; j2 < 16; j2++) tr[j2] = trans[i * 16 + j2];

    float fv = (i == START_ID) ? 0.0f : NEGV;

    // software prefetch pipeline, depth 4
    float fpre[4];
#pragma unroll
    for (int p = 0; p < 4; p++) fpre[p] = g_feats[p][i];

    for (int t = 0; t < SLEN; t += 4) {
#pragma unroll
        for (int u = 0; u < 4; u++) {
            float v[16];
            int idx[16];
#pragma unroll
            for (int j2 = 0; j2 < 16; j2++) {
                v[j2] = __shfl_sync(0xffffffff, fv, j2) + tr[j2];
                idx[j2] = j2;
            }
            // argmax tree (strict > keeps first-max index, matching jnp.argmax)
#pragma unroll
            for (int stride = 1; stride < 16; stride <<= 1) {
#pragma unroll
                for (int j2 = 0; j2 < 16; j2 += 2 * stride) {
                    if (v[j2 + stride] > v[j2]) {
                        v[j2] = v[j2 + stride];
                        idx[j2] = idx[j2 + stride];
                    }
                }
            }
            if (lane < 16) bp[(t + u) * 16 + i] = (unsigned char)idx[0];
            fv = v[0] + fpre[u];
            fpre[u] = g_feats[t + u + 4][i];  // padded array: always in-bounds
        }
    }

    // terminal
    float tv = (lane < 16) ? (fv + trans[STOP_ID * 16 + i]) : -3.4e38f;
    int ti = i;
#pragma unroll
    for (int s = 8; s >= 1; s >>= 1) {
        float ov = __shfl_down_sync(0xffffffff, tv, s);
        int oi = __shfl_down_sync(0xffffffff, ti, s);
        if (ov > tv || (ov == tv && oi < ti)) { tv = ov; ti = oi; }
    }
    if (lane == 0) {
        if (out_size > 0) out[0] = tv;
        int tag = ti;
        for (int t = SLEN - 1; t >= 0; t--) {
            if (1 + t < out_size) out[1 + t] = (float)tag;
            tag = bp[t * 16 + tag];
        }
    }
}

// ---------------- launch ----------------
extern "C" void kernel_launch(void* const* d_in, const int* in_sizes, int n_in,
                              void* d_out, int out_size) {
    const int*   sent = (const int*)d_in[0];
    const float* emb  = (const float*)d_in[1];
    const float* WihF = (const float*)d_in[2];
    const float* WhhF = (const float*)d_in[3];
    const float* bihF = (const float*)d_in[4];
    const float* bhhF = (const float*)d_in[5];
    const float* WihB = (const float*)d_in[6];
    const float* WhhB = (const float*)d_in[7];
    const float* bihB = (const float*)d_in[8];
    const float* bhhB = (const float*)d_in[9];
    const float* h0   = (const float*)d_in[10];
    const float* c0   = (const float*)d_in[11];
    const float* Wt   = (const float*)d_in[12];
    const float* bt   = (const float*)d_in[13];
    const float* trn  = (const float*)d_in[14];
    float* out = (float*)d_out;

    cudaFuncSetAttribute(k_viterbi, cudaFuncAttributeMaxDynamicSharedMemorySize,
                         SLEN * 16 + 1024);

    dim3 gxg(G4 / BN, SLEN / BM, 2);
    k_xg<<<gxg, 256>>>(sent, emb, WihF, WihB, bihF, bhhF, bihB, bhhB);

    k_lstm<<<16, 256>>>(WhhF, WhhB, h0, c0);

    k_feats<<<SLEN, 128>>>(Wt, bt);

    k_viterbi<<<1, 32, SLEN * 16>>>(trn, out, out_size);
}

// round 4
// speedup vs baseline: 1.7498x; 1.0020x over previous
#include <cuda_runtime.h>
#include <cstdint>

// Problem constants
#define SLEN 8192
#define EDIM 512
#define HDIM 256
#define G4   1024   // 4*H
#define NTAG 16
#define NEGV (-10000.0f)
#define START_ID 14
#define STOP_ID  15

// ---------------- scratch (device globals; no allocations) ----------------
__device__ float g_xg[2][SLEN][G4];          // precomputed input projections (+bias)
__device__ float g_hs[2][SLEN][HDIM];        // hs[0][t]=fwd h_t ; hs[1][t]=bwd h at forward-time t
__device__ float g_feats[SLEN + 8][NTAG];    // padded for viterbi prefetch

// ---------------- small asm helpers ----------------
__device__ __forceinline__ void fma2(unsigned long long& acc, unsigned long long a,
                                     unsigned long long b) {
    asm("fma.rn.f32x2 %0, %1, %2, %0;" : "+l"(acc) : "l"(a), "l"(b));
}
__device__ __forceinline__ unsigned long long pack2(float x, float y) {
    unsigned long long r;
    asm("mov.b64 %0, {%1, %2};" : "=l"(r) : "f"(x), "f"(y));
    return r;
}
__device__ __forceinline__ float2 unpack2(unsigned long long v) {
    float2 r;
    asm("mov.b64 {%0, %1}, %2;" : "=f"(r.x), "=f"(r.y) : "l"(v));
    return r;
}
__device__ __forceinline__ float fast_sigmoid(float x) {
    return 1.0f / (1.0f + __expf(-x));
}
__device__ __forceinline__ float fast_tanh(float x) {
    return 2.0f / (1.0f + __expf(-2.0f * x)) - 1.0f;
}
__device__ __forceinline__ uint32_t smem_u32(const void* p) {
    uint32_t a;
    asm("{ .reg .u64 t; cvta.to.shared.u64 t, %1; cvt.u32.u64 %0, t; }"
        : "=r"(a) : "l"(p));
    return a;
}
__device__ __forceinline__ uint32_t mapa_rank(uint32_t addr, uint32_t rank) {
    uint32_t r;
    asm("mapa.shared::cluster.u32 %0, %1, %2;" : "=r"(r) : "r"(addr), "r"(rank));
    return r;
}
__device__ __forceinline__ void st_async_b64(uint32_t daddr, unsigned long long v,
                                             uint32_t maddr) {
    asm volatile(
        "st.async.shared::cluster.mbarrier::complete_tx::bytes.b64 [%0], %1, [%2];"
        :: "r"(daddr), "l"(v), "r"(maddr) : "memory");
}
__device__ __forceinline__ void mbar_init(uint32_t maddr, uint32_t cnt) {
    asm volatile("mbarrier.init.shared.b64 [%0], %1;" :: "r"(maddr), "r"(cnt) : "memory");
}
__device__ __forceinline__ void mbar_expect(uint32_t maddr, uint32_t bytes) {
    asm volatile("mbarrier.arrive.expect_tx.shared.b64 _, [%0], %1;"
                 :: "r"(maddr), "r"(bytes) : "memory");
}
__device__ __forceinline__ void mbar_wait(uint32_t maddr, uint32_t parity) {
    asm volatile(
        "{\n\t.reg .pred P1;\n\t"
        "WL%=:\n\t"
        "mbarrier.try_wait.parity.acquire.cta.shared::cta.b64 P1, [%0], %1, 0x989680;\n\t"
        "@P1 bra WD%=;\n\t"
        "bra WL%=;\n\t"
        "WD%=:\n\t}"
        :: "r"(maddr), "r"(parity) : "memory");
}
#define CLUSTER_SYNC() do { \
    asm volatile("barrier.cluster.arrive.aligned;" ::: "memory"); \
    asm volatile("barrier.cluster.wait.aligned;" ::: "memory"); } while (0)

// ---------------- kernel 1: xg = gather(embedding) @ Wih.T + (bih+bhh) ----------------
#define BM 64
#define BN 64
#define BK 32
__global__ void __launch_bounds__(256) k_xg(
    const int* __restrict__ sent, const float* __restrict__ emb,
    const float* __restrict__ WihF, const float* __restrict__ WihB,
    const float* __restrict__ bihF, const float* __restrict__ bhhF,
    const float* __restrict__ bihB, const float* __restrict__ bhhB) {
    int dir = blockIdx.z;
    int t0 = blockIdx.y * BM;
    int n0 = blockIdx.x * BN;
    const float* Wih = dir ? WihB : WihF;

    __shared__ float As[BK][BM + 4];
    __shared__ float Bs[BK][BN + 4];
    __shared__ int sidx[BM];
    __shared__ float biassm[BN];

    int tid = threadIdx.x;  // 256
    if (tid < BM) {
        int t = t0 + tid;
        int s = dir ? (SLEN - 1 - t) : t;
        sidx[tid] = sent[s];
    }
    if (tid < BN) {
        int n = n0 + tid;
        biassm[tid] = dir ? (bihB[n] + bhhB[n]) : (bihF[n] + bhhF[n]);
    }
    __syncthreads();

    float acc[4][4];
#pragma unroll
    for (int i = 0; i < 4; i++)
#pragma unroll
        for (int j = 0; j < 4; j++) acc[i][j] = 0.0f;

    int tm = (tid & 15) * 4;
    int tn = (tid >> 4) * 4;
    int lm = tid >> 2;           // 0..63 : row (t or n) for loading
    int lk = (tid & 3) * 8;      // k offset in tile

    for (int k0 = 0; k0 < EDIM; k0 += BK) {
        {
            const float4* src = (const float4*)(emb + (size_t)sidx[lm] * EDIM + k0 + lk);
            float4 a0 = src[0], a1 = src[1];
            As[lk + 0][lm] = a0.x; As[lk + 1][lm] = a0.y;
            As[lk + 2][lm] = a0.z; As[lk + 3][lm] = a0.w;
            As[lk + 4][lm] = a1.x; As[lk + 5][lm] = a1.y;
            As[lk + 6][lm] = a1.z; As[lk + 7][lm] = a1.w;
        }
        {
            const float4* src = (const float4*)(Wih + (size_t)(n0 + lm) * EDIM + k0 + lk);
            float4 b0 = src[0], b1 = src[1];
            Bs[lk + 0][lm] = b0.x; Bs[lk + 1][lm] = b0.y;
            Bs[lk + 2][lm] = b0.z; Bs[lk + 3][lm] = b0.w;
            Bs[lk + 4][lm] = b1.x; Bs[lk + 5][lm] = b1.y;
            Bs[lk + 6][lm] = b1.z; Bs[lk + 7][lm] = b1.w;
        }
        __syncthreads();
#pragma unroll
        for (int kk = 0; kk < BK; kk++) {
            float4 av = *(const float4*)&As[kk][tm];
            float4 bv = *(const float4*)&Bs[kk][tn];
            float a[4] = {av.x, av.y, av.z, av.w};
            float b[4] = {bv.x, bv.y, bv.z, bv.w};
#pragma unroll
            for (int i = 0; i < 4; i++)
#pragma unroll
                for (int j = 0; j < 4; j++) acc[i][j] += a[i] * b[j];
        }
        __syncthreads();
    }
#pragma unroll
    for (int i = 0; i < 4; i++)
#pragma unroll
        for (int j = 0; j < 4; j++)
            g_xg[dir][t0 + tm + i][n0 + tn + j] = acc[i][j] + biassm[tn + j];
}

// ---------------- kernel 2: bidirectional LSTM recurrence (cluster + DSMEM) ----------------
// Grid = 16 CTAs, cluster (8,1,1): cluster 0 = fwd, cluster 1 = bwd.
// CTA rank r owns h[32r, 32r+32). Warp w owns h-elements eoff=r*32+w*4 .. +4 and
// computes ALL FOUR gates for them: 16 gate rows/warp, 2 lanes per row
// (row = lane>>1, half = lane&1, q = row>>2, d = row&3).
// Per step, per warp (no CTA barrier anywhere in the loop):
//   mbar_wait -> matvec (reg weights, f32x2) -> shfl_xor pair-sum -> 4 shfl gate
//   gather -> cell update (all lanes, redundant by d=lane&3) -> st.async.b64 of
//   h-pairs to all 8 CTAs' double-buffered hbuf (128 tx-updates per barrier).

template <int P>
__device__ __forceinline__ void lstm_step(
    int t, int dir, int tid, int lane, int eoff, int grow,
    const unsigned long long* __restrict__ wl,
    float (*hbuf)[256],
    uint32_t mb_cur, uint32_t mb_nxt, uint32_t& ph_cur,
    uint32_t dd, uint32_t dm,
    float& c, float& xcur) {
    if (t > 0) { mbar_wait(mb_cur, ph_cur); ph_cur ^= 1; }
    if (tid == 0 && t + 1 < SLEN) mbar_expect(mb_nxt, 1024);

    // ---- matvec half-row: 128 MACs via 64 packed fma.f32x2 ----
    const ulonglong2* h2 = (const ulonglong2*)&hbuf[P][(lane & 1) * 128];
    unsigned long long a0 = 0ull, a1 = 0ull, a2 = 0ull, a3 = 0ull;
#pragma unroll
    for (int m = 0; m < 32; m++) {
        ulonglong2 hv = h2[m];
        if (m & 1) { fma2(a2, wl[2 * m], hv.x); fma2(a3, wl[2 * m + 1], hv.y); }
        else       { fma2(a0, wl[2 * m], hv.x); fma2(a1, wl[2 * m + 1], hv.y); }
    }
    float2 f0 = unpack2(a0), f1 = unpack2(a1), f2 = unpack2(a2), f3 = unpack2(a3);
    float part = ((f0.x + f0.y) + (f1.x + f1.y)) + ((f2.x + f2.y) + (f3.x + f3.y));
    // pair-sum across halves; add xg (valid on even lanes, which are all shfl sources)
    float gate = part + __shfl_xor_sync(0xffffffffu, part, 1) + xcur;
    if (!(lane & 1) && t + 1 < SLEN) xcur = g_xg[dir][t + 1][grow];

    // gather i,f,g,o for h-element d = lane&3 (sources: even lanes 2*(4q+d))
    int d = lane & 3;
    float gi = __shfl_sync(0xffffffffu, gate, 2 * d);
    float gf = __shfl_sync(0xffffffffu, gate, 2 * d + 8);
    float gg = __shfl_sync(0xffffffffu, gate, 2 * d + 16);
    float go = __shfl_sync(0xffffffffu, gate, 2 * d + 24);
    float ig = fast_sigmoid(gi);
    float fg = fast_sigmoid(gf);
    float gv = fast_tanh(gg);
    float og = fast_sigmoid(go);
    c = fg * c + ig * gv;
    float h = og * fast_tanh(c);

    int tstore = dir ? (SLEN - 1 - t) : t;
    if (lane < 4) g_hs[dir][tstore][eoff + d] = h;
    if (t + 1 < SLEN) {
        // pack adjacent h pair, 16 lanes deliver b64 to 8 ranks (lane>>1)
        float hlo = __shfl_sync(0xffffffffu, h, (lane & 1) * 2);
        float hhi = __shfl_sync(0xffffffffu, h, (lane & 1) * 2 + 1);
        if (lane < 16) st_async_b64(dd, pack2(hlo, hhi), dm);
    }
}

__global__ void __launch_bounds__(256, 1) __cluster_dims__(8, 1, 1)
k_lstm(const float* __restrict__ WhhF, const float* __restrict__ WhhB,
       const float* __restrict__ h0, const float* __restrict__ c0) {
    int dir = blockIdx.x >> 3;
    int r = blockIdx.x & 7;            // == cluster rank
    int tid = threadIdx.x;
    int w = tid >> 5, lane = tid & 31;
    int row = lane >> 1;               // local gate row within warp: 0..15
    int q = row >> 2, d = row & 3;
    int eoff = r * 32 + w * 4;         // first h-element owned by this warp
    int grow = q * 256 + eoff + d;     // global gate row in Whh / xg
    const float* Whh = dir ? WhhB : WhhF;

    __shared__ __align__(16) float hbuf[2][256];
    __shared__ __align__(8) unsigned long long mbar[2];

    // register-resident weight half-row: 128 floats = 64 packed f32x2
    unsigned long long wl[64];
    {
        const float2* wrow = (const float2*)(Whh + (size_t)grow * HDIM) + (lane & 1) * 64;
#pragma unroll
        for (int m = 0; m < 64; m++) { float2 v = wrow[m]; wl[m] = pack2(v.x, v.y); }
    }

    uint32_t hb0 = smem_u32(&hbuf[0][0]), hb1 = smem_u32(&hbuf[1][0]);
    uint32_t mb0 = smem_u32(&mbar[0]),    mb1 = smem_u32(&mbar[1]);
    if (tid == 0) { mbar_init(mb0, 1); mbar_init(mb1, 1); }
    hbuf[0][tid] = h0[dir * HDIM + tid];

    float c = c0[dir * HDIM + eoff + (lane & 3)];   // replicated per d-group
    float xcur = (!(lane & 1)) ? g_xg[dir][0][grow] : 0.0f;

    // per-lane st.async destinations (lanes 0..15 used): h pair (lane&1), rank lane>>1
    uint32_t rk = ((uint32_t)lane >> 1) & 7u;
    uint32_t off = (uint32_t)(eoff + (lane & 1) * 2) * 4u;
    uint32_t dd0 = mapa_rank(hb0 + off, rk);
    uint32_t dd1 = mapa_rank(hb1 + off, rk);
    uint32_t dm0 = mapa_rank(mb0, rk);
    uint32_t dm1 = mapa_rank(mb1, rk);

    __syncthreads();
    CLUSTER_SYNC();   // mbarriers + hbuf[0] visible cluster-wide before any st.async

    uint32_t ph0 = 0, ph1 = 0;
#pragma unroll 1
    for (int t = 0; t < SLEN; t += 2) {
        lstm_step<0>(t,     dir, tid, lane, eoff, grow, wl, hbuf,
                     mb0, mb1, ph0, dd1, dm1, c, xcur);
        lstm_step<1>(t + 1, dir, tid, lane, eoff, grow, wl, hbuf,
                     mb1, mb0, ph1, dd0, dm0, c, xcur);
    }
    CLUSTER_SYNC();   // no CTA exits while peers' st.async may be in flight
}

// ---------------- kernel 3: feats[t] = concat(hf,hb) @ W_tag.T + b_tag ----------------
__global__ void __launch_bounds__(128) k_feats(const float* __restrict__ Wt,
                                               const float* __restrict__ bt) {
    int t = blockIdx.x;
    __shared__ float hsm[512];
    __shared__ float Wsm[NTAG * 513];
    int tid = threadIdx.x;  // 128
    {
        float4* h4 = (float4*)hsm;
        if (tid < 64) h4[tid] = ((const float4*)g_hs[0][t])[tid];
        else h4[tid] = ((const float4*)g_hs[1][t])[tid - 64];
    }
    for (int i = tid; i < NTAG * 512; i += 128) {
        int tg = i >> 9, k = i & 511;
        Wsm[tg * 513 + k] = Wt[i];
    }
    __syncthreads();
    int tg = tid >> 3, seg = tid & 7;
    float acc = 0.0f;
#pragma unroll 8
    for (int m = 0; m < 64; m++) {
        int k = seg + 8 * m;  // stride-8: conflict-free banks
        acc += hsm[k] * Wsm[tg * 513 + k];
    }
    acc += __shfl_xor_sync(0xffffffff, acc, 1);
    acc += __shfl_xor_sync(0xffffffff, acc, 2);
    acc += __shfl_xor_sync(0xffffffff, acc, 4);
    if (seg == 0) g_feats[t][tg] = acc + bt[tg];
}

// ---------------- kernel 4: Viterbi + backtrace (1 warp) ----------------
__global__ void k_viterbi(const float* __restrict__ trans, float* __restrict__ out,
                          int out_size) {
    extern __shared__ unsigned char bp[];  // [SLEN][16] backpointers
    int lane = threadIdx.x;                // 32 threads
    int i = lane & 15;

    float tr[16];
#pragma unroll
    for (int j2 = 0; j2 < 16; j2++) tr[j2] = trans[i * 16 + j2];

    float fv = (i == START_ID) ? 0.0f : NEGV;

    // software prefetch pipeline, depth 4
    float fpre[4];
#pragma unroll
    for (int p = 0; p < 4; p++) fpre[p] = g_feats[p][i];

    for (int t = 0; t < SLEN; t += 4) {
#pragma unroll
        for (int u = 0; u < 4; u++) {
            float v[16];
            int idx[16];
#pragma unroll
            for (int j2 = 0; j2 < 16; j2++) {
                v[j2] = __shfl_sync(0xffffffff, fv, j2) + tr[j2];
                idx[j2] = j2;
            }
            // argmax tree (strict > keeps first-max index, matching jnp.argmax)
#pragma unroll
            for (int stride = 1; stride < 16; stride <<= 1) {
#pragma unroll
                for (int j2 = 0; j2 < 16; j2 += 2 * stride) {
                    if (v[j2 + stride] > v[j2]) {
                        v[j2] = v[j2 + stride];
                        idx[j2] = idx[j2 + stride];
                    }
                }
            }
            if (lane < 16) bp[(t + u) * 16 + i] = (unsigned char)idx[0];
            fv = v[0] + fpre[u];
            fpre[u] = g_feats[t + u + 4][i];  // padded array: always in-bounds
        }
    }

    // terminal
    float tv = (lane < 16) ? (fv + trans[STOP_ID * 16 + i]) : -3.4e38f;
    int ti = i;
#pragma unroll
    for (int s = 8; s >= 1; s >>= 1) {
        float ov = __shfl_down_sync(0xffffffff, tv, s);
        int oi = __shfl_down_sync(0xffffffff, ti, s);
        if (ov > tv || (ov == tv && oi < ti)) { tv = ov; ti = oi; }
    }
    if (lane == 0) {
        if (out_size > 0) out[0] = tv;
        int tag = ti;
        for (int t = SLEN - 1; t >= 0; t--) {
            if (1 + t < out_size) out[1 + t] = (float)tag;
            tag = bp[t * 16 + tag];
        }
    }
}

// ---------------- launch ----------------
extern "C" void kernel_launch(void* const* d_in, const int* in_sizes, int n_in,
                              void* d_out, int out_size) {
    const int*   sent = (const int*)d_in[0];
    const float* emb  = (const float*)d_in[1];
    const float* WihF = (const float*)d_in[2];
    const float* WhhF = (const float*)d_in[3];
    const float* bihF = (const float*)d_in[4];
    const float* bhhF = (const float*)d_in[5];
    const float* WihB = (const float*)d_in[6];
    const float* WhhB = (const float*)d_in[7];
    const float* bihB = (const float*)d_in[8];
    const float* bhhB = (const float*)d_in[9];
    const float* h0   = (const float*)d_in[10];
    const float* c0   = (const float*)d_in[11];
    const float* Wt   = (const float*)d_in[12];
    const float* bt   = (const float*)d_in[13];
    const float* trn  = (const float*)d_in[14];
    float* out = (float*)d_out;

    cudaFuncSetAttribute(k_viterbi, cudaFuncAttributeMaxDynamicSharedMemorySize,
                         SLEN * 16 + 1024);

    dim3 gxg(G4 / BN, SLEN / BM, 2);
    k_xg<<<gxg, 256>>>(sent, emb, WihF, WihB, bihF, bhhF, bihB, bhhB);

    k_lstm<<<16, 256>>>(WhhF, WhhB, h0, c0);

    k_feats<<<SLEN, 128>>>(Wt, bt);

    k_viterbi<<<1, 32, SLEN * 16>>>(trn, out, out_size);
}